// round 13
// baseline (speedup 1.0000x reference)
#include <cuda_runtime.h>

// SplineNetwork: 2 queries/warp (16 lanes each), smem-rank selection.
// B=16384 queries, 128x128 regular grid, K=9 NN + Keys cubic conv.
//   d_in[0] = x (16384,2) f32 | d_in[1] = weights (16384,1) f32
//   d_in[2] = control_points (16384,2) f32, cp[i*128+j] = (t_i, t_j)
// Output: (out (16384,1), x (16384,2)) -> 49152 floats.
//
// Interior (i0 in [1,125]^2): floor-4x4 window {i0-1..i0+2}, 16 candidates,
// element e = 4r+c == row-major == ascending global index (R10-certified
// window: in-window 9th-NN <= 3.25h^2, excluded >= 4h^2).
// D bit-matches reference: rn(rn(x2s + rn(rn(cx^2)+rn(cy^2)))
//                              - 2*fma(x1,cy,rn(x0*cx))).
// Selection: stable rank via smem exchange --
//   rank_e = #{ j : Dj < De  or  (Dj == De and j < e) },  sel = rank < 9
// == lexicographic (D, ascending global index) == jax.lax.top_k stability.
// Edge queries (~5%) take the R8-certified full-warp 5x5 25-candidate path.

#define NGRID 128
#define KNN   9

__device__ __forceinline__ float process_q25(
    float2 xv, const float* __restrict__ cp, const float* __restrict__ wts,
    float inv_h, int lane)
{
    const unsigned FULL = 0xffffffffu;
    int nix = __float2int_rn((xv.x + 1.0f) * 63.5f);
    int niy = __float2int_rn((xv.y + 1.0f) * 63.5f);
    int sx = min(max(nix - 2, 0), NGRID - 5);
    int sy = min(max(niy - 2, 0), NGRID - 5);

    int row = (lane * 205) >> 10;      // lane / 5
    int col = lane - row * 5;
    bool sentinel = lane >= 25;
    int ix = sx + (sentinel ? 0 : row);
    int iy = sy + (sentinel ? 0 : col);

    float cx = __ldg(&cp[ix << 8]);
    float cy = __ldg(&cp[2 * iy + 1]);
    float wv = __ldg(&wts[(ix << 7) + iy]);

    float x2s = __fadd_rn(__fmul_rn(xv.x, xv.x), __fmul_rn(xv.y, xv.y));
    float c2  = __fadd_rn(__fmul_rn(cx, cx), __fmul_rn(cy, cy));
    float dot = __fmaf_rn(xv.y, cy, __fmul_rn(xv.x, cx));
    float D   = __fsub_rn(__fadd_rn(x2s, c2), __fmul_rn(2.0f, dot));
    if (sentinel) D = __int_as_float(0x7f800000);

    float S = D;
#pragma unroll
    for (int k = 2; k <= 32; k <<= 1) {
#pragma unroll
        for (int j = k >> 1; j > 0; j >>= 1) {
            float Sp = __shfl_xor_sync(FULL, S, j);
            bool keepmin = ((lane & j) == 0) == ((lane & k) == 0);
            S = keepmin ? fminf(S, Sp) : fmaxf(S, Sp);
        }
    }
    float T9 = __shfl_sync(FULL, S, KNN - 1);

    unsigned below  = (1u << lane) - 1u;
    unsigned strict = __ballot_sync(FULL, D < T9);
    unsigned tie    = __ballot_sync(FULL, D == T9);
    bool sel = (D < T9) ||
               ((D == T9) && (__popc(tie & below) < KNN - __popc(strict)));

    float dxv = xv.x - cx, dyv = xv.y - cy;
    float a = sqrtf(fmaf(dxv, dxv, dyv * dyv)) * inv_h;
    float p1 = fmaf(fmaf(1.5f, a, -2.5f), a * a, 1.0f);
    float p2 = fmaf(fmaf(fmaf(-0.5f, a, 2.5f), a, -4.0f), a, 2.0f);
    float cv = (a < 1.0f) ? p1 : ((a < 2.0f) ? p2 : 0.0f);

    float val = sel ? (wv * cv) : 0.0f;
#pragma unroll
    for (int s = 16; s; s >>= 1)
        val += __shfl_xor_sync(FULL, val, s);
    return val;
}

__global__ __launch_bounds__(256) void spline_sr_kernel(
    const float* __restrict__ x,
    const float* __restrict__ wts,
    const float* __restrict__ cp,
    float* __restrict__ out,
    int batch)
{
    const unsigned FULL = 0xffffffffu;
    __shared__ float sD[256];

    int tid  = threadIdx.x;
    int lane = tid & 31;
    int e    = lane & 15;              // element index within query (0..15)
    int half = lane >> 4;
    int w = blockIdx.x * (blockDim.x >> 5) + (tid >> 5);
    int q = 2 * w + half;              // this half's query

    float2 xq = __ldg((const float2*)x + q);

    // bandwidth h = ||x[0]-x[1]|| (smooth epilogue term, warp-uniform)
    float4 h4 = __ldg((const float4*)x);
    float hdx = h4.x - h4.z, hdy = h4.y - h4.w;
    float inv_h = rsqrtf(fmaf(hdx, hdx, hdy * hdy));

    int i0x = (int)floorf((xq.x + 1.0f) * 63.5f);
    int i0y = (int)floorf((xq.y + 1.0f) * 63.5f);
    bool edge = (i0x < 1) | (i0x > 125) | (i0y < 1) | (i0y > 125);
    unsigned eb = __ballot_sync(FULL, edge);

    if (eb == 0u) {
        // ---- fast path: floor-4x4, element e = 4r+c (ascending global idx)
        int ix = i0x - 1 + (e >> 2);
        int iy = i0y - 1 + (e & 3);

        float cx = __ldg(&cp[ix << 8]);        // x-coord of grid row ix
        float cy = __ldg(&cp[2 * iy + 1]);     // y-coord of grid col iy
        float wv = __ldg(&wts[(ix << 7) + iy]);

        // certified D chain
        float x2s = __fadd_rn(__fmul_rn(xq.x, xq.x), __fmul_rn(xq.y, xq.y));
        float c2  = __fadd_rn(__fmul_rn(cx, cx), __fmul_rn(cy, cy));
        float dot = __fmaf_rn(xq.y, cy, __fmul_rn(xq.x, cx));
        float D   = __fsub_rn(__fadd_rn(x2s, c2), __fmul_rn(2.0f, dot));

        // ---- smem exchange: my group's 16 D values
        sD[tid] = D;
        __syncwarp(FULL);
        const float4* grp = (const float4*)&sD[(tid & ~31) | (half << 4)];
        float4 v0 = grp[0], v1 = grp[1], v2 = grp[2], v3 = grp[3];
        float arr[16] = { v0.x, v0.y, v0.z, v0.w,  v1.x, v1.y, v1.z, v1.w,
                          v2.x, v2.y, v2.z, v2.w,  v3.x, v3.y, v3.z, v3.w };

        // ---- stable rank (independent compares, no warp-wide chain)
        int rank = 0;
#pragma unroll
        for (int j = 0; j < 16; ++j) {
            bool b = (arr[j] < D) || ((arr[j] == D) && (j < e));
            rank += b ? 1 : 0;
        }
        bool sel = rank < KNN;

        // ---- Keys cubic conv epilogue
        float dxv = xq.x - cx, dyv = xq.y - cy;
        float a = sqrtf(fmaf(dxv, dxv, dyv * dyv)) * inv_h;
        float p1 = fmaf(fmaf(1.5f, a, -2.5f), a * a, 1.0f);
        float p2 = fmaf(fmaf(fmaf(-0.5f, a, 2.5f), a, -4.0f), a, 2.0f);
        float cv = (a < 1.0f) ? p1 : ((a < 2.0f) ? p2 : 0.0f);

        float val = sel ? (wv * cv) : 0.0f;
        // 4-step half-warp sum (both halves in parallel)
#pragma unroll
        for (int s = 8; s; s >>= 1)
            val += __shfl_xor_sync(FULL, val, s);

        if (e == 0) {
            out[q] = val;
            ((float2*)(out + batch))[q] = xq;
        }
    } else {
        // ---- edge fallback: R8-certified 25-candidate path, both queries
        int qb = 2 * w;
        float2 xv0 = __ldg((const float2*)x + qb);
        float2 xv1 = __ldg((const float2*)x + qb + 1);
        float v0 = process_q25(xv0, cp, wts, inv_h, lane);
        float v1 = process_q25(xv1, cp, wts, inv_h, lane);
        if (lane == 0) {
            out[qb]     = v0;
            out[qb + 1] = v1;
            float2* xp = (float2*)(out + batch);
            xp[qb] = xv0; xp[qb + 1] = xv1;
        }
    }
}

extern "C" void kernel_launch(void* const* d_in, const int* in_sizes, int n_in,
                              void* d_out, int out_size)
{
    const float* x  = (const float*)d_in[0];
    const float* w  = (const float*)d_in[1];
    const float* cp = (const float*)d_in[2];
    float* out = (float*)d_out;
    int batch = in_sizes[0] / 2;              // 16384
    int block = 256;                          // 8 warps = 16 queries per CTA
    int qpb = (block / 32) * 2;
    int grid = (batch + qpb - 1) / qpb;       // 1024, exact
    spline_sr_kernel<<<grid, block>>>(x, w, cp, out, batch);
    (void)n_in; (void)out_size;
}

// round 14
// speedup vs baseline: 1.0257x; 1.0257x over previous
#include <cuda_runtime.h>

// SplineNetwork: 2 queries/warp (16 lanes each), smem-rank selection,
// shared linspace table. B=16384 queries, 128x128 grid, K=9 NN + cubic conv.
//   d_in[0] = x (16384,2) f32 | d_in[1] = weights (16384,1) f32
//   d_in[2] = control_points (16384,2) f32, cp[i*128+j] = (t_i, t_j)
// Output: (out (16384,1), x (16384,2)) -> 49152 floats.
//
// t[i] = cp[2i+1] = linspace[i] serves BOTH axes bit-exactly (meshgrid).
// Interior (i0 in [1,125]^2): floor-4x4 window, 16 candidates, element
// e = 4r+c == ascending global index (R10/R13-certified margins).
// D bit-matches reference: rn(rn(x2s + rn(rn(cx^2)+rn(cy^2)))
//                              - 2*fma(x1,cy,rn(x0*cx))).
// Stable rank (D, ascending index) == lax.top_k; sel iff rank < 9.
// Edge queries -> R8-certified full-warp 5x5 25-candidate path.

#define NGRID 128
#define KNN   9

__device__ __forceinline__ float process_q25(
    float2 xv, const float* __restrict__ t,
    const float* __restrict__ wts, float inv_h, int lane)
{
    const unsigned FULL = 0xffffffffu;
    int nix = __float2int_rn((xv.x + 1.0f) * 63.5f);
    int niy = __float2int_rn((xv.y + 1.0f) * 63.5f);
    int sx = min(max(nix - 2, 0), NGRID - 5);
    int sy = min(max(niy - 2, 0), NGRID - 5);

    int row = (lane * 205) >> 10;      // lane / 5
    int col = lane - row * 5;
    bool sentinel = lane >= 25;
    int ix = sx + (sentinel ? 0 : row);
    int iy = sy + (sentinel ? 0 : col);

    float cx = t[ix];
    float cy = t[iy];
    float wv = __ldg(&wts[(ix << 7) + iy]);

    float x2s = __fadd_rn(__fmul_rn(xv.x, xv.x), __fmul_rn(xv.y, xv.y));
    float c2  = __fadd_rn(__fmul_rn(cx, cx), __fmul_rn(cy, cy));
    float dot = __fmaf_rn(xv.y, cy, __fmul_rn(xv.x, cx));
    float D   = __fsub_rn(__fadd_rn(x2s, c2), __fmul_rn(2.0f, dot));
    if (sentinel) D = __int_as_float(0x7f800000);

    float S = D;
#pragma unroll
    for (int k = 2; k <= 32; k <<= 1) {
#pragma unroll
        for (int j = k >> 1; j > 0; j >>= 1) {
            float Sp = __shfl_xor_sync(FULL, S, j);
            bool keepmin = ((lane & j) == 0) == ((lane & k) == 0);
            S = keepmin ? fminf(S, Sp) : fmaxf(S, Sp);
        }
    }
    float T9 = __shfl_sync(FULL, S, KNN - 1);

    unsigned below  = (1u << lane) - 1u;
    unsigned strict = __ballot_sync(FULL, D < T9);
    unsigned tie    = __ballot_sync(FULL, D == T9);
    bool sel = (D < T9) ||
               ((D == T9) && (__popc(tie & below) < KNN - __popc(strict)));

    float dxv = xv.x - cx, dyv = xv.y - cy;
    float a = sqrtf(fmaf(dxv, dxv, dyv * dyv)) * inv_h;
    float p1 = fmaf(fmaf(1.5f, a, -2.5f), a * a, 1.0f);
    float p2 = fmaf(fmaf(fmaf(-0.5f, a, 2.5f), a, -4.0f), a, 2.0f);
    float cv = (a < 1.0f) ? p1 : ((a < 2.0f) ? p2 : 0.0f);

    float val = sel ? (wv * cv) : 0.0f;
#pragma unroll
    for (int s = 16; s; s >>= 1)
        val += __shfl_xor_sync(FULL, val, s);
    return val;
}

__global__ __launch_bounds__(128) void spline_sr2_kernel(
    const float* __restrict__ x,
    const float* __restrict__ wts,
    const float* __restrict__ cp,
    float* __restrict__ out,
    int batch)
{
    const unsigned FULL = 0xffffffffu;
    __shared__ float ts[NGRID];
    __shared__ float sD[128];

    int tid  = threadIdx.x;
    int lane = tid & 31;
    int e    = lane & 15;              // element index within query (0..15)
    int half = lane >> 4;
    int w = blockIdx.x * (blockDim.x >> 5) + (tid >> 5);
    int q = 2 * w + half;              // this half's query

    // earliest loads: query point + bandwidth endpoints (independent LDGs)
    float2 xq = __ldg((const float2*)x + q);
    float4 h4 = __ldg((const float4*)x);

    // linspace table (serves both axes bit-exactly): t[i] = cp[2i+1]
    ts[tid] = cp[2 * tid + 1];         // blockDim == 128 == NGRID
    __syncthreads();

    float hdx = h4.x - h4.z, hdy = h4.y - h4.w;
    float inv_h = rsqrtf(fmaf(hdx, hdx, hdy * hdy));

    int i0x = __float2int_rd((xq.x + 1.0f) * 63.5f);
    int i0y = __float2int_rd((xq.y + 1.0f) * 63.5f);
    bool edge = (i0x < 1) | (i0x > 125) | (i0y < 1) | (i0y > 125);
    unsigned eb = __ballot_sync(FULL, edge);

    if (eb == 0u) {
        // ---- fast path: floor-4x4, element e = 4r+c (ascending global idx)
        int ix = i0x - 1 + (e >> 2);
        int iy = i0y - 1 + (e & 3);

        float wv = __ldg(&wts[(ix << 7) + iy]);   // the one dependent LDG
        float cx = ts[ix];
        float cy = ts[iy];

        // certified D chain
        float x2s = __fadd_rn(__fmul_rn(xq.x, xq.x), __fmul_rn(xq.y, xq.y));
        float c2  = __fadd_rn(__fmul_rn(cx, cx), __fmul_rn(cy, cy));
        float dot = __fmaf_rn(xq.y, cy, __fmul_rn(xq.x, cx));
        float D   = __fsub_rn(__fadd_rn(x2s, c2), __fmul_rn(2.0f, dot));

        // ---- smem exchange: my group's 16 D values
        sD[tid] = D;
        __syncwarp(FULL);
        const float4* grp = (const float4*)&sD[(tid & ~31) | (half << 4)];
        float4 v0 = grp[0], v1 = grp[1], v2 = grp[2], v3 = grp[3];
        float arr[16] = { v0.x, v0.y, v0.z, v0.w,  v1.x, v1.y, v1.z, v1.w,
                          v2.x, v2.y, v2.z, v2.w,  v3.x, v3.y, v3.z, v3.w };

        // ---- stable rank (independent compares, no warp-wide chain)
        int rank = 0;
#pragma unroll
        for (int j = 0; j < 16; ++j) {
            bool b = (arr[j] < D) || ((arr[j] == D) && (j < e));
            rank += b ? 1 : 0;
        }
        bool sel = rank < KNN;

        // ---- Keys cubic conv epilogue
        float dxv = xq.x - cx, dyv = xq.y - cy;
        float a = sqrtf(fmaf(dxv, dxv, dyv * dyv)) * inv_h;
        float p1 = fmaf(fmaf(1.5f, a, -2.5f), a * a, 1.0f);
        float p2 = fmaf(fmaf(fmaf(-0.5f, a, 2.5f), a, -4.0f), a, 2.0f);
        float cv = (a < 1.0f) ? p1 : ((a < 2.0f) ? p2 : 0.0f);

        float val = sel ? (wv * cv) : 0.0f;
        // 4-step half-warp sum (both halves in parallel)
#pragma unroll
        for (int s = 8; s; s >>= 1)
            val += __shfl_xor_sync(FULL, val, s);

        if (e == 0) {
            out[q] = val;
            ((float2*)(out + batch))[q] = xq;
        }
    } else {
        // ---- edge fallback: R8-certified 25-candidate path, both queries
        int qb = 2 * w;
        float2 xv0 = __ldg((const float2*)x + qb);
        float2 xv1 = __ldg((const float2*)x + qb + 1);
        float v0 = process_q25(xv0, ts, wts, inv_h, lane);
        float v1 = process_q25(xv1, ts, wts, inv_h, lane);
        if (lane == 0) {
            out[qb]     = v0;
            out[qb + 1] = v1;
            float2* xp = (float2*)(out + batch);
            xp[qb] = xv0; xp[qb + 1] = xv1;
        }
    }
}

extern "C" void kernel_launch(void* const* d_in, const int* in_sizes, int n_in,
                              void* d_out, int out_size)
{
    const float* x  = (const float*)d_in[0];
    const float* w  = (const float*)d_in[1];
    const float* cp = (const float*)d_in[2];
    float* out = (float*)d_out;
    int batch = in_sizes[0] / 2;              // 16384
    int block = 128;                          // 4 warps = 8 queries per CTA
    int qpb = (block / 32) * 2;
    int grid = (batch + qpb - 1) / qpb;       // 2048, exact
    spline_sr2_kernel<<<grid, block>>>(x, w, cp, out, batch);
    (void)n_in; (void)out_size;
}